// round 2
// baseline (speedup 1.0000x reference)
#include <cuda_runtime.h>
#include <math.h>

#define HIN 1536
#define BM  128
#define BK  32
#define NT  (HIN / BK)   // 48 k-tiles

using u64 = unsigned long long;

__device__ __forceinline__ u64 pk2(float lo, float hi) {
    u64 r; asm("mov.b64 %0, {%1, %2};" : "=l"(r) : "f"(lo), "f"(hi)); return r;
}
__device__ __forceinline__ void upk2(u64 v, float& lo, float& hi) {
    asm("mov.b64 {%0, %1}, %2;" : "=f"(lo), "=f"(hi) : "l"(v));
}
__device__ __forceinline__ u64 ffma2(u64 a, u64 b, u64 c) {
#if defined(__CUDA_ARCH__) && (__CUDA_ARCH__ >= 1000)
    u64 d; asm("fma.rn.f32x2 %0, %1, %2, %3;" : "=l"(d) : "l"(a), "l"(b), "l"(c)); return d;
#else
    float al, ah, bl, bh, cl, ch;
    upk2(a, al, ah); upk2(b, bl, bh); upk2(c, cl, ch);
    return pk2(fmaf(al, bl, cl), fmaf(ah, bh, ch));
#endif
}

// One stream: rows = 8192, K = 1536, N = D. Block computes BM=128 rows x D cols,
// fully fused epilogue (bias + exact GELU + LayerNorm + gamma/beta).
template<int D>
__device__ __forceinline__ void run_stream(
    const float* __restrict__ X, const float* __restrict__ W,
    const float* __restrict__ Bias, const float* __restrict__ Gam, const float* __restrict__ Bet,
    float* __restrict__ OUT, int tile, float* __restrict__ AsF, u64* __restrict__ Bs)
{
    constexpr int TN = D / 16;            // 4 / 2 / 1
    constexpr int NB = (BK * D) / 256;    // B-tile elems per thread: 8 / 4 / 2
    const int tid = threadIdx.x;
    const int tx  = tid & 15;             // n-group (16)
    const int ty  = tid >> 4;             // m-group (16), rows ty*8 .. ty*8+7
    const float* __restrict__ Ablk = X + (size_t)tile * BM * HIN;

    float4 va[4];
    float  vb[NB];
    u64 acc[4][TN];
#pragma unroll
    for (int i = 0; i < 4; ++i)
#pragma unroll
        for (int j = 0; j < TN; ++j) acc[i][j] = 0ull;

    // ---- prologue: load + store tile 0 ----
#pragma unroll
    for (int p = 0; p < 4; ++p) {
        int f4 = tid + p * 256;
        int r = f4 >> 3, c4 = f4 & 7;
        va[p] = *(const float4*)(Ablk + (size_t)r * HIN + c4 * 4);
    }
#pragma unroll
    for (int q = 0; q < NB; ++q) vb[q] = W[tid + q * 256];

#pragma unroll
    for (int p = 0; p < 4; ++p) {
        int f4 = tid + p * 256;
        int r = f4 >> 3, c4 = f4 & 7;
        const float* vp = (const float*)&va[p];
#pragma unroll
        for (int u = 0; u < 4; ++u) {
            int kk = c4 * 4 + u;
            AsF[kk * BM + (r ^ (kk & 28))] = vp[u];   // XOR swizzle: conflict-free
        }
    }
#pragma unroll
    for (int q = 0; q < NB; ++q) { int idx = tid + q * 256; Bs[idx] = pk2(vb[q], vb[q]); }
    __syncthreads();

    // ---- main loop: register-prefetch next tile under current compute ----
    for (int t = 0; t < NT; ++t) {
        const bool more = (t + 1 < NT);
        const int k0n = (t + 1) * BK;
        if (more) {
#pragma unroll
            for (int p = 0; p < 4; ++p) {
                int f4 = tid + p * 256;
                int r = f4 >> 3, c4 = f4 & 7;
                va[p] = *(const float4*)(Ablk + (size_t)r * HIN + k0n + c4 * 4);
            }
#pragma unroll
            for (int q = 0; q < NB; ++q) vb[q] = W[(size_t)k0n * D + tid + q * 256];
        }

#pragma unroll
        for (int k = 0; k < BK; ++k) {
            const int msk = k & 28;
            float4 a0 = *(const float4*)(AsF + k * BM + ((ty * 8)     ^ msk));
            float4 a1 = *(const float4*)(AsF + k * BM + ((ty * 8 + 4) ^ msk));
            u64 ap[4] = { pk2(a0.x, a0.y), pk2(a0.z, a0.w), pk2(a1.x, a1.y), pk2(a1.z, a1.w) };
            u64 bd[TN];
            const u64* brow = Bs + k * D + tx * TN;
            if constexpr (TN == 4) {
                ulonglong2 p0 = *(const ulonglong2*)(brow);
                ulonglong2 p1 = *(const ulonglong2*)(brow + 2);
                bd[0] = p0.x; bd[1] = p0.y; bd[2] = p1.x; bd[3] = p1.y;
            } else if constexpr (TN == 2) {
                ulonglong2 p0 = *(const ulonglong2*)(brow);
                bd[0] = p0.x; bd[1] = p0.y;
            } else {
                bd[0] = brow[0];
            }
#pragma unroll
            for (int j = 0; j < TN; ++j)
#pragma unroll
                for (int i = 0; i < 4; ++i)
                    acc[i][j] = ffma2(ap[i], bd[j], acc[i][j]);
        }
        __syncthreads();
        if (more) {
#pragma unroll
            for (int p = 0; p < 4; ++p) {
                int f4 = tid + p * 256;
                int r = f4 >> 3, c4 = f4 & 7;
                const float* vp = (const float*)&va[p];
#pragma unroll
                for (int u = 0; u < 4; ++u) {
                    int kk = c4 * 4 + u;
                    AsF[kk * BM + (r ^ (kk & 28))] = vp[u];
                }
            }
#pragma unroll
            for (int q = 0; q < NB; ++q) { int idx = tid + q * 256; Bs[idx] = pk2(vb[q], vb[q]); }
            __syncthreads();
        }
    }

    // ---- fused epilogue: bias + exact GELU + LayerNorm over D + gamma/beta ----
    float bias[TN], gam[TN], bet[TN];
#pragma unroll
    for (int j = 0; j < TN; ++j) {
        int n = tx * TN + j;
        bias[j] = __ldg(Bias + n); gam[j] = __ldg(Gam + n); bet[j] = __ldg(Bet + n);
    }
    const float invD = 1.0f / (float)D;
#pragma unroll
    for (int r = 0; r < 8; ++r) {
        float v[TN];
#pragma unroll
        for (int j = 0; j < TN; ++j) {
            float lo, hi; upk2(acc[r >> 1][j], lo, hi);
            v[j] = (r & 1) ? hi : lo;
        }
        float s = 0.f, s2 = 0.f;
#pragma unroll
        for (int j = 0; j < TN; ++j) {
            float x = v[j] + bias[j];
            float g = 0.5f * x * (1.0f + erff(x * 0.7071067811865475f));  // exact GELU
            v[j] = g; s += g; s2 += g * g;
        }
        // row's D columns live in one 16-lane half-warp (tx = low 4 lane bits)
#pragma unroll
        for (int o = 8; o >= 1; o >>= 1) {
            s  += __shfl_xor_sync(0xffffffffu, s,  o);
            s2 += __shfl_xor_sync(0xffffffffu, s2, o);
        }
        float mu  = s * invD;
        float var = fmaxf(s2 * invD - mu * mu, 0.0f);
        float rs  = rsqrtf(var + 1e-5f);
        int m = tile * BM + ty * 8 + r;
        float* dst = OUT + (size_t)m * D + tx * TN;
#pragma unroll
        for (int j = 0; j < TN; ++j) v[j] = (v[j] - mu) * rs * gam[j] + bet[j];
        if constexpr (TN == 4)      *(float4*)dst = make_float4(v[0], v[1], v[2], v[3]);
        else if constexpr (TN == 2) *(float2*)dst = make_float2(v[0], v[1]);
        else                        dst[0] = v[0];
    }
}

__global__ void __launch_bounds__(256, 2) fused_gemm_gelu_ln(
    const float* __restrict__ x0, const float* __restrict__ w0, const float* __restrict__ b0,
    const float* __restrict__ g0, const float* __restrict__ t0,
    const float* __restrict__ x1, const float* __restrict__ w1, const float* __restrict__ b1,
    const float* __restrict__ g1, const float* __restrict__ t1,
    const float* __restrict__ x2, const float* __restrict__ w2, const float* __restrict__ b2,
    const float* __restrict__ g2, const float* __restrict__ t2,
    const float* __restrict__ x3, const float* __restrict__ w3, const float* __restrict__ b3,
    const float* __restrict__ g3, const float* __restrict__ t3,
    float* __restrict__ out)
{
    __shared__ __align__(16) float AsF[BK * BM];   // 16 KB, transposed+swizzled A tile
    __shared__ __align__(16) u64  Bs[BK * 64];     // 16 KB, {w,w}-duplicated B tile
    const int s    = blockIdx.x & 3;               // interleave streams for balance
    const int tile = blockIdx.x >> 2;              // 64 tiles per stream
    if (s == 0)      run_stream<64>(x0, w0, b0, g0, t0, out,           tile, AsF, Bs);
    else if (s == 1) run_stream<32>(x1, w1, b1, g1, t1, out + 524288,  tile, AsF, Bs);
    else if (s == 2) run_stream<32>(x2, w2, b2, g2, t2, out + 786432,  tile, AsF, Bs);
    else             run_stream<16>(x3, w3, b3, g3, t3, out + 1048576, tile, AsF, Bs);
}

extern "C" void kernel_launch(void* const* d_in, const int* in_sizes, int n_in,
                              void* d_out, int out_size)
{
    const float* x0 = (const float*)d_in[0];
    const float* w0 = (const float*)d_in[1];
    const float* b0 = (const float*)d_in[2];
    const float* g0 = (const float*)d_in[3];
    const float* t0 = (const float*)d_in[4];
    const float* x1 = (const float*)d_in[5];
    const float* w1 = (const float*)d_in[6];
    const float* b1 = (const float*)d_in[7];
    const float* g1 = (const float*)d_in[8];
    const float* t1 = (const float*)d_in[9];
    const float* x2 = (const float*)d_in[10];
    const float* w2 = (const float*)d_in[11];
    const float* b2 = (const float*)d_in[12];
    const float* g2 = (const float*)d_in[13];
    const float* t2 = (const float*)d_in[14];
    const float* x3 = (const float*)d_in[15];
    const float* w3 = (const float*)d_in[16];
    const float* b3 = (const float*)d_in[17];
    const float* g3 = (const float*)d_in[18];
    const float* t3 = (const float*)d_in[19];
    float* out = (float*)d_out;

    // grid: 4 streams x (8192/128) tiles, stream-interleaved
    fused_gemm_gelu_ln<<<256, 256>>>(
        x0, w0, b0, g0, t0,
        x1, w1, b1, g1, t1,
        x2, w2, b2, g2, t2,
        x3, w3, b3, g3, t3,
        out);
}